// round 1
// baseline (speedup 1.0000x reference)
#include <cuda_runtime.h>
#include <math.h>

#define L_STEPS 24
#define NN 16384
#define LN (24*16384)          // 393216
#define HD 128
#define DIN 136
#define KTOT 264               // 136 + 128
#define GATES 512

// ---------------- device scratch (feature-major / column-major layouts) ----------------
__device__ float g_x[(size_t)DIN * LN];        // [k][LN]  lstm_in (raw acts, BN folded into weights)
__device__ float g_W[(size_t)KTOT * GATES];    // [k][512] combined (scaled Wih | Whh)
__device__ float g_cbias[GATES];
__device__ float g_stats[128];                 // [0:64) sums, [64:128) sumsq (f:0..31, o:32..63)
__device__ float g_gh[(size_t)HD * NN];        // [d][N]
__device__ float g_gc[(size_t)HD * NN];
__device__ float g_gates[(size_t)GATES * NN];  // [c][N]
__device__ float g_h[(size_t)HD * NN];         // [d][N]
__device__ float g_c[(size_t)HD * NN];

__device__ __forceinline__ float sigf(float x) { return 1.0f / (1.0f + expf(-x)); }

// ---------------- zero init (h, c, stats) ----------------
__global__ void zero_kernel() {
    size_t i = (size_t)blockIdx.x * blockDim.x + threadIdx.x;
    size_t hn = (size_t)HD * NN;
    if (i < hn)      g_h[i] = 0.0f;
    else if (i < 2*hn) g_c[i - hn] = 0.0f;
    if (i < 128) g_stats[i] = 0.0f;
}

// ---------------- build lstm_in columns: op, attr copied; leaky(filter@WfT+bf), leaky(out@WoT+bo) raw ----------------
__global__ __launch_bounds__(256) void build_x_kernel(
    const float* __restrict__ op, const float* __restrict__ attr,
    const float* __restrict__ filt, const float* __restrict__ outp,
    const float* __restrict__ Wf, const float* __restrict__ bf,
    const float* __restrict__ Wo, const float* __restrict__ bo)
{
    __shared__ __align__(16) float sWfT[74 * 32];   // [k][j]
    __shared__ __align__(16) float sWoT[32 * 32];
    __shared__ float sbf[32], sbo[32];
    int tid = threadIdx.x;
    for (int i = tid; i < 74 * 32; i += 256) { int j = i / 74, k = i % 74; sWfT[k * 32 + j] = Wf[i]; }
    for (int i = tid; i < 32 * 32; i += 256) { int j = i / 32, k = i % 32; sWoT[k * 32 + j] = Wo[i]; }
    if (tid < 32) { sbf[tid] = bf[tid]; sbo[tid] = bo[tid]; }
    __syncthreads();

    size_t r = (size_t)blockIdx.x * 256 + tid;   // row in [0, LN)

    // op / attr copy into columns 0..71 (coalesced column-major stores)
    const float* opr = op + r * 16;
    #pragma unroll
    for (int k = 0; k < 16; k++) g_x[(size_t)k * LN + r] = opr[k];
    const float* atr = attr + r * 56;
    #pragma unroll 8
    for (int k = 0; k < 56; k++) g_x[(size_t)(16 + k) * LN + r] = atr[k];

    float acc[32];
    // filter branch
    #pragma unroll
    for (int j = 0; j < 32; j++) acc[j] = sbf[j];
    const float* frow = filt + r * 74;
    for (int k = 0; k < 74; k++) {
        float fv = __ldg(&frow[k]);
        const float4* wrow = (const float4*)&sWfT[k * 32];
        #pragma unroll
        for (int j4 = 0; j4 < 8; j4++) {
            float4 w = wrow[j4];
            acc[j4*4+0] += fv * w.x; acc[j4*4+1] += fv * w.y;
            acc[j4*4+2] += fv * w.z; acc[j4*4+3] += fv * w.w;
        }
    }
    #pragma unroll
    for (int j = 0; j < 32; j++) {
        float v = acc[j]; v = v > 0.0f ? v : 0.01f * v;
        g_x[(size_t)(72 + j) * LN + r] = v;
    }
    // output branch
    #pragma unroll
    for (int j = 0; j < 32; j++) acc[j] = sbo[j];
    const float* orow = outp + r * 32;
    for (int k = 0; k < 32; k++) {
        float ov = __ldg(&orow[k]);
        const float4* wrow = (const float4*)&sWoT[k * 32];
        #pragma unroll
        for (int j4 = 0; j4 < 8; j4++) {
            float4 w = wrow[j4];
            acc[j4*4+0] += ov * w.x; acc[j4*4+1] += ov * w.y;
            acc[j4*4+2] += ov * w.z; acc[j4*4+3] += ov * w.w;
        }
    }
    #pragma unroll
    for (int j = 0; j < 32; j++) {
        float v = acc[j]; v = v > 0.0f ? v : 0.01f * v;
        g_x[(size_t)(104 + j) * LN + r] = v;
    }
}

// ---------------- BN stats: sum & sumsq over LN rows of columns 72..135 ----------------
__global__ void stats_kernel() {
    int f = blockIdx.x;                 // 0..63
    size_t col = (size_t)(72 + f) * LN;
    float s = 0.0f, q = 0.0f;
    for (size_t i = (size_t)blockIdx.y * blockDim.x + threadIdx.x; i < LN;
         i += (size_t)gridDim.y * blockDim.x) {
        float v = g_x[col + i];
        s += v; q += v * v;
    }
    // warp reduce
    for (int o = 16; o > 0; o >>= 1) {
        s += __shfl_down_sync(0xffffffffu, s, o);
        q += __shfl_down_sync(0xffffffffu, q, o);
    }
    __shared__ float shs[8], shq[8];
    int lane = threadIdx.x & 31, w = threadIdx.x >> 5;
    if (lane == 0) { shs[w] = s; shq[w] = q; }
    __syncthreads();
    if (threadIdx.x == 0) {
        float ts = 0.0f, tq = 0.0f;
        for (int i = 0; i < 8; i++) { ts += shs[i]; tq += shq[i]; }
        atomicAdd(&g_stats[f], ts);
        atomicAdd(&g_stats[64 + f], tq);
    }
}

// ---------------- fold BN into weights; build combined W [264][512] and cbias ----------------
__global__ void prep_kernel(
    const float* __restrict__ g1, const float* __restrict__ beta1,
    const float* __restrict__ g2, const float* __restrict__ beta2,
    const float* __restrict__ Wih, const float* __restrict__ Whh,
    const float* __restrict__ bih, const float* __restrict__ bhh)
{
    __shared__ float ss[64], st[64];
    int tid = threadIdx.x;  // 512 threads
    if (tid < 64) {
        float mean = g_stats[tid] * (1.0f / (float)LN);
        float var  = g_stats[64 + tid] * (1.0f / (float)LN) - mean * mean;
        float gg = tid < 32 ? g1[tid] : g2[tid - 32];
        float bb = tid < 32 ? beta1[tid] : beta2[tid - 32];
        float sc = gg * rsqrtf(var + 1e-5f);
        ss[tid] = sc;
        st[tid] = bb - mean * sc;
    }
    __syncthreads();
    int c = tid;
    const float* wr = Wih + (size_t)c * DIN;
    float cb = bih[c] + bhh[c];
    #pragma unroll
    for (int j = 0; j < 32; j++) cb += st[j] * wr[72 + j];
    #pragma unroll
    for (int j = 0; j < 32; j++) cb += st[32 + j] * wr[104 + j];
    g_cbias[c] = cb;
    for (int k = 0; k < KTOT; k++) {
        float w;
        if (k < 72)        w = wr[k];
        else if (k < 104)  w = wr[k] * ss[k - 72];
        else if (k < 136)  w = wr[k] * ss[32 + (k - 104)];
        else               w = Whh[(size_t)c * HD + (k - 136)];
        g_W[(size_t)k * GATES + c] = w;
    }
}

// ---------------- per-step neighbor gather: gh/gc [d][N] ----------------
__global__ void gather_kernel(const int* __restrict__ mapping, int l) {
    int n = blockIdx.x * blockDim.x + threadIdx.x;   // gridDim.x = NN/256
    int d = blockIdx.y;                              // 0..127
    const int* mp = mapping + ((size_t)l * NN + n) * 2;
    int m0 = __ldg(&mp[0]), m1 = __ldg(&mp[1]);
    size_t base = (size_t)d * NN;
    float gh = 0.0f, gc = 0.0f;
    if (m0 > 0) { gh += g_h[base + m0 - 1]; gc += g_c[base + m0 - 1]; }
    if (m1 > 0) { gh += g_h[base + m1 - 1]; gc += g_c[base + m1 - 1]; }
    g_gh[base + n] = 0.5f * gh;
    g_gc[base + n] = 0.5f * gc;
}

// ---------------- per-step gates GEMM: [x_t | gh] @ W + cbias -> gates [c][N] ----------------
// M=16384 (BM=128), N=512 (BN=64), K=264 (BK=8). 256 threads, 8x4 register tile.
__global__ __launch_bounds__(256) void gates_gemm(int l) {
    __shared__ __align__(16) float As[8][128];
    __shared__ __align__(16) float Bs[8][64];
    int tid = threadIdx.x;
    int m0 = blockIdx.x * 128;
    int c0 = blockIdx.y * 64;
    int tx = tid & 15;      // 16 col-groups of 4
    int ty = tid >> 4;      // 16 row-groups of 8
    int lak = tid >> 5;             // 0..7  (k within chunk)
    int lam = (tid & 31) * 4;       // 0..124
    int lbk = tid >> 5;             // 0..7
    int lbc = (tid * 2) & 63;

    float acc[8][4];
    #pragma unroll
    for (int i = 0; i < 8; i++)
        #pragma unroll
        for (int j = 0; j < 4; j++) acc[i][j] = 0.0f;

    size_t xoff = (size_t)l * NN;

    for (int k0 = 0; k0 < KTOT; k0 += 8) {
        int k = k0 + lak;
        const float* src = (k < DIN) ? (g_x + (size_t)k * LN + xoff)
                                     : (g_gh + (size_t)(k - DIN) * NN);
        float4 av = *(const float4*)(src + m0 + lam);
        *(float4*)&As[lak][lam] = av;
        float2 bv = *(const float2*)(g_W + (size_t)(k0 + lbk) * GATES + c0 + lbc);
        *(float2*)&Bs[lbk][lbc] = bv;
        __syncthreads();
        #pragma unroll
        for (int kk = 0; kk < 8; kk++) {
            float4 a0 = *(float4*)&As[kk][ty * 8];
            float4 a1 = *(float4*)&As[kk][ty * 8 + 4];
            float4 b  = *(float4*)&Bs[kk][tx * 4];
            float a[8] = {a0.x, a0.y, a0.z, a0.w, a1.x, a1.y, a1.z, a1.w};
            float bb[4] = {b.x, b.y, b.z, b.w};
            #pragma unroll
            for (int i = 0; i < 8; i++)
                #pragma unroll
                for (int j = 0; j < 4; j++)
                    acc[i][j] += a[i] * bb[j];
        }
        __syncthreads();
    }

    #pragma unroll
    for (int j = 0; j < 4; j++) {
        int c = c0 + tx * 4 + j;
        float cb = __ldg(&g_cbias[c]);
        float4 v0 = { acc[0][j] + cb, acc[1][j] + cb, acc[2][j] + cb, acc[3][j] + cb };
        float4 v1 = { acc[4][j] + cb, acc[5][j] + cb, acc[6][j] + cb, acc[7][j] + cb };
        float* dst = g_gates + (size_t)c * NN + m0 + ty * 8;
        *(float4*)dst = v0;
        *(float4*)(dst + 4) = v1;
    }
}

// ---------------- LSTM cell elementwise ----------------
__global__ void cell_kernel() {
    size_t i = (size_t)blockIdx.x * blockDim.x + threadIdx.x;   // i = d*N + n, d<128
    float iv = g_gates[i];
    float fv = g_gates[i + (size_t)128 * NN];
    float gv = g_gates[i + (size_t)256 * NN];
    float ov = g_gates[i + (size_t)384 * NN];
    float gc = g_gc[i];
    float cn = sigf(fv) * gc + sigf(iv) * tanhf(gv);
    g_c[i] = cn;
    g_h[i] = sigf(ov) * tanhf(cn);
}

// ---------------- head MLP: sigmoid((h @ W1^T + b1) @ W2^T + b2) ----------------
__global__ void head_kernel(const float* __restrict__ W1, const float* __restrict__ b1,
                            const float* __restrict__ W2, const float* __restrict__ b2,
                            float* __restrict__ out, int rows)
{
    __shared__ float sW1[20 * 128];
    __shared__ float sb1[20], sW2[20];
    __shared__ float sb2;
    int tid = threadIdx.x;
    for (int i = tid; i < 20 * 128; i += 256) sW1[i] = W1[i];
    if (tid < 20) { sb1[tid] = b1[tid]; sW2[tid] = W2[tid]; }
    if (tid == 0) sb2 = b2[0];
    __syncthreads();
    int b = blockIdx.x * 256 + tid;
    if (b >= rows) return;
    float z1[20];
    #pragma unroll
    for (int j = 0; j < 20; j++) z1[j] = sb1[j];
    for (int k = 0; k < 128; k++) {
        float hv = g_h[(size_t)k * NN + b];
        #pragma unroll
        for (int j = 0; j < 20; j++) z1[j] += hv * sW1[j * 128 + k];
    }
    float z = sb2;
    #pragma unroll
    for (int j = 0; j < 20; j++) z += z1[j] * sW2[j];
    out[b] = 1.0f / (1.0f + expf(-z));
}

// ---------------- launch ----------------
extern "C" void kernel_launch(void* const* d_in, const int* in_sizes, int n_in,
                              void* d_out, int out_size)
{
    const float* op    = (const float*)d_in[0];
    const float* attr  = (const float*)d_in[1];
    const float* filt  = (const float*)d_in[2];
    const float* outp  = (const float*)d_in[3];
    const int*   mapping = (const int*)d_in[4];
    // batch_size may or may not appear as an input (scalar). Detect via size.
    int wb = (in_sizes[5] == 1) ? 6 : 5;
    const float* Wf    = (const float*)d_in[wb + 0];
    const float* bf    = (const float*)d_in[wb + 1];
    const float* Wo    = (const float*)d_in[wb + 2];
    const float* bo    = (const float*)d_in[wb + 3];
    const float* g1    = (const float*)d_in[wb + 4];
    const float* beta1 = (const float*)d_in[wb + 5];
    const float* g2    = (const float*)d_in[wb + 6];
    const float* beta2 = (const float*)d_in[wb + 7];
    const float* Wih   = (const float*)d_in[wb + 8];
    const float* Whh   = (const float*)d_in[wb + 9];
    const float* bih   = (const float*)d_in[wb + 10];
    const float* bhh   = (const float*)d_in[wb + 11];
    const float* W1    = (const float*)d_in[wb + 12];
    const float* b1    = (const float*)d_in[wb + 13];
    const float* W2    = (const float*)d_in[wb + 14];
    const float* b2    = (const float*)d_in[wb + 15];
    float* outptr = (float*)d_out;

    // init h=c=0, stats=0
    zero_kernel<<<(2 * HD * NN) / 256, 256>>>();
    // encoders -> g_x (raw activations, op/attr copied)
    build_x_kernel<<<LN / 256, 256>>>(op, attr, filt, outp, Wf, bf, Wo, bo);
    // BN stats
    stats_kernel<<<dim3(64, 12), 256>>>();
    // fold BN + biases, build combined weight matrix
    prep_kernel<<<1, 512>>>(g1, beta1, g2, beta2, Wih, Whh, bih, bhh);

    // reverse scan: step t uses layer l = 23 - t
    for (int t = 0; t < L_STEPS; t++) {
        int l = L_STEPS - 1 - t;
        gather_kernel<<<dim3(NN / 256, HD), 256>>>(mapping, l);
        gates_gemm<<<dim3(NN / 128, GATES / 64), 256>>>(l);
        cell_kernel<<<(HD * NN) / 256, 256>>>();
    }

    // head over first out_size rows (== batch_size)
    head_kernel<<<(out_size + 255) / 256, 256>>>(W1, b1, W2, b2, outptr, out_size);
}

// round 2
// speedup vs baseline: 1.6229x; 1.6229x over previous
#include <cuda_runtime.h>
#include <math.h>

#define L_STEPS 24
#define NN 16384
#define LN (24*16384)          // 393216
#define HD 128
#define DIN 136
#define KTOT 264               // 136 + 128
#define GATES 512

// ---------------- device scratch (feature-major / column-major layouts) ----------------
__device__ float g_x[(size_t)DIN * LN];        // [k][LN]  lstm_in, tf32-rounded
__device__ float g_W[(size_t)KTOT * GATES];    // [k][512] combined weights, tf32-rounded
__device__ float g_cbias[GATES];
__device__ float g_stats[128];                 // sums / sumsq
__device__ float g_ss[64], g_st[64];           // BN fold scale/shift
__device__ float g_gh[(size_t)HD * NN];        // [d][N]  tf32-rounded
__device__ float g_gc[(size_t)HD * NN];
__device__ float g_gates[(size_t)GATES * NN];  // [c][N]
__device__ float g_h[(size_t)HD * NN];         // [d][N]
__device__ float g_c[(size_t)HD * NN];

__device__ __forceinline__ float sigf(float x) { return 1.0f / (1.0f + expf(-x)); }
__device__ __forceinline__ float tf32r(float x) {
    float y;
    asm("cvt.rna.tf32.f32 %0, %1;" : "=f"(y) : "f"(x));
    return y;
}

// ---------------- zero init (h, c, stats) ----------------
__global__ void zero_kernel() {
    size_t i = (size_t)blockIdx.x * blockDim.x + threadIdx.x;
    size_t hn = (size_t)HD * NN;
    if (i < hn)        g_h[i] = 0.0f;
    else if (i < 2*hn) g_c[i - hn] = 0.0f;
    if (i < 128) g_stats[i] = 0.0f;
}

// ---------------- build lstm_in columns (tf32-rounded) ----------------
__global__ __launch_bounds__(256) void build_x_kernel(
    const float* __restrict__ op, const float* __restrict__ attr,
    const float* __restrict__ filt, const float* __restrict__ outp,
    const float* __restrict__ Wf, const float* __restrict__ bf,
    const float* __restrict__ Wo, const float* __restrict__ bo)
{
    __shared__ __align__(16) float sWfT[74 * 32];   // [k][j]
    __shared__ __align__(16) float sWoT[32 * 32];
    __shared__ float sbf[32], sbo[32];
    int tid = threadIdx.x;
    for (int i = tid; i < 74 * 32; i += 256) { int j = i / 74, k = i % 74; sWfT[k * 32 + j] = Wf[i]; }
    for (int i = tid; i < 32 * 32; i += 256) { int j = i / 32, k = i % 32; sWoT[k * 32 + j] = Wo[i]; }
    if (tid < 32) { sbf[tid] = bf[tid]; sbo[tid] = bo[tid]; }
    __syncthreads();

    size_t r = (size_t)blockIdx.x * 256 + tid;

    const float* opr = op + r * 16;
    #pragma unroll
    for (int k = 0; k < 16; k++) g_x[(size_t)k * LN + r] = tf32r(opr[k]);
    const float* atr = attr + r * 56;
    #pragma unroll 8
    for (int k = 0; k < 56; k++) g_x[(size_t)(16 + k) * LN + r] = tf32r(atr[k]);

    float acc[32];
    #pragma unroll
    for (int j = 0; j < 32; j++) acc[j] = sbf[j];
    const float* frow = filt + r * 74;
    for (int k = 0; k < 74; k++) {
        float fv = __ldg(&frow[k]);
        const float4* wrow = (const float4*)&sWfT[k * 32];
        #pragma unroll
        for (int j4 = 0; j4 < 8; j4++) {
            float4 w = wrow[j4];
            acc[j4*4+0] += fv * w.x; acc[j4*4+1] += fv * w.y;
            acc[j4*4+2] += fv * w.z; acc[j4*4+3] += fv * w.w;
        }
    }
    #pragma unroll
    for (int j = 0; j < 32; j++) {
        float v = acc[j]; v = v > 0.0f ? v : 0.01f * v;
        g_x[(size_t)(72 + j) * LN + r] = v;   // raw (stats need exact); rounded later? no: BN folded into W, so A must be raw*? 
    }
    #pragma unroll
    for (int j = 0; j < 32; j++) acc[j] = sbo[j];
    const float* orow = outp + r * 32;
    for (int k = 0; k < 32; k++) {
        float ov = __ldg(&orow[k]);
        const float4* wrow = (const float4*)&sWoT[k * 32];
        #pragma unroll
        for (int j4 = 0; j4 < 8; j4++) {
            float4 w = wrow[j4];
            acc[j4*4+0] += ov * w.x; acc[j4*4+1] += ov * w.y;
            acc[j4*4+2] += ov * w.z; acc[j4*4+3] += ov * w.w;
        }
    }
    #pragma unroll
    for (int j = 0; j < 32; j++) {
        float v = acc[j]; v = v > 0.0f ? v : 0.01f * v;
        g_x[(size_t)(104 + j) * LN + r] = v;
    }
}

// ---------------- BN stats over columns 72..135 ----------------
__global__ void stats_kernel() {
    int f = blockIdx.x;                 // 0..63
    size_t col = (size_t)(72 + f) * LN;
    float s = 0.0f, q = 0.0f;
    for (size_t i = (size_t)blockIdx.y * blockDim.x + threadIdx.x; i < LN;
         i += (size_t)gridDim.y * blockDim.x) {
        float v = g_x[col + i];
        s += v; q += v * v;
    }
    for (int o = 16; o > 0; o >>= 1) {
        s += __shfl_down_sync(0xffffffffu, s, o);
        q += __shfl_down_sync(0xffffffffu, q, o);
    }
    __shared__ float shs[8], shq[8];
    int lane = threadIdx.x & 31, w = threadIdx.x >> 5;
    if (lane == 0) { shs[w] = s; shq[w] = q; }
    __syncthreads();
    if (threadIdx.x == 0) {
        float ts = 0.0f, tq = 0.0f;
        for (int i = 0; i < 8; i++) { ts += shs[i]; tq += shq[i]; }
        atomicAdd(&g_stats[f], ts);
        atomicAdd(&g_stats[64 + f], tq);
    }
}

// ---------------- tf32-round the BN'd activation columns (after stats) ----------------
__global__ void round_x_kernel() {
    // round columns 72..135 in place (BN is folded into W, raw act just needs tf32)
    size_t i = (size_t)blockIdx.x * blockDim.x + threadIdx.x;   // over 64*LN
    size_t base = (size_t)72 * LN;
    g_x[base + i] = tf32r(g_x[base + i]);
}

// ---------------- BN fold scale/shift ----------------
__global__ void fold_kernel(
    const float* __restrict__ g1, const float* __restrict__ beta1,
    const float* __restrict__ g2, const float* __restrict__ beta2)
{
    int tid = threadIdx.x;   // 64
    float mean = g_stats[tid] * (1.0f / (float)LN);
    float var  = g_stats[64 + tid] * (1.0f / (float)LN) - mean * mean;
    float gg = tid < 32 ? g1[tid] : g2[tid - 32];
    float bb = tid < 32 ? beta1[tid] : beta2[tid - 32];
    float sc = gg * rsqrtf(var + 1e-5f);
    g_ss[tid] = sc;
    g_st[tid] = bb - mean * sc;
}

// ---------------- combined bias ----------------
__global__ void cbias_kernel(
    const float* __restrict__ Wih,
    const float* __restrict__ bih, const float* __restrict__ bhh)
{
    int c = threadIdx.x;   // 512
    const float* wr = Wih + (size_t)c * DIN;
    float cb = bih[c] + bhh[c];
    #pragma unroll
    for (int j = 0; j < 32; j++) cb += g_st[j] * wr[72 + j];
    #pragma unroll
    for (int j = 0; j < 32; j++) cb += g_st[32 + j] * wr[104 + j];
    g_cbias[c] = cb;
}

// ---------------- weight matrix build (parallel over k), tf32-rounded ----------------
__global__ void weight_kernel(const float* __restrict__ Wih, const float* __restrict__ Whh) {
    int k = blockIdx.x;           // 0..263
    int c = threadIdx.x;          // 512
    float w;
    if (k < 72)        w = Wih[(size_t)c * DIN + k];
    else if (k < 104)  w = Wih[(size_t)c * DIN + k] * g_ss[k - 72];
    else if (k < 136)  w = Wih[(size_t)c * DIN + k] * g_ss[32 + (k - 104)];
    else               w = Whh[(size_t)c * HD + (k - 136)];
    g_W[(size_t)k * GATES + c] = tf32r(w);
}

// ---------------- per-step neighbor gather (tf32-round gh; gc stays fp32) ----------------
__global__ void gather_kernel(const int* __restrict__ mapping, int l) {
    int n = blockIdx.x * blockDim.x + threadIdx.x;
    int d = blockIdx.y;
    const int* mp = mapping + ((size_t)l * NN + n) * 2;
    int m0 = __ldg(&mp[0]), m1 = __ldg(&mp[1]);
    size_t base = (size_t)d * NN;
    float gh = 0.0f, gc = 0.0f;
    if (m0 > 0) { gh += g_h[base + m0 - 1]; gc += g_c[base + m0 - 1]; }
    if (m1 > 0) { gh += g_h[base + m1 - 1]; gc += g_c[base + m1 - 1]; }
    g_gh[base + n] = tf32r(0.5f * gh);
    g_gc[base + n] = 0.5f * gc;
}

// ---------------- tf32 tensor-core gates GEMM ----------------
// M=16384 (BM=128), N=512 (BN=64), K=264 (BK=8). 256 threads = 8 warps (4x2),
// warp tile 32x32 via m16n8k8: 2 m-tiles x 4 n-tiles.
#define ASTRIDE 136
#define BSTRIDE 72
__global__ __launch_bounds__(256) void gates_gemm_tc(int l) {
    __shared__ __align__(16) float As[8][ASTRIDE];   // [k][m]
    __shared__ __align__(16) float Bs[8][BSTRIDE];   // [k][c]
    int tid = threadIdx.x;
    int wid = tid >> 5, lane = tid & 31;
    int m0 = blockIdx.x * 128;
    int c0 = blockIdx.y * 64;
    int wm = (wid & 3) * 32;        // warp row offset
    int wn = (wid >> 2) * 32;       // warp col offset
    int gid = lane >> 2, tig = lane & 3;

    float acc[2][4][4];
    #pragma unroll
    for (int mi = 0; mi < 2; mi++)
        #pragma unroll
        for (int ni = 0; ni < 4; ni++)
            #pragma unroll
            for (int r = 0; r < 4; r++) acc[mi][ni][r] = 0.0f;

    int lak = tid >> 5;             // 0..7
    int lam = (lane) * 4;           // 0..124
    int lbk = tid >> 5;
    int lbc = lane * 2;             // 0..62

    size_t xoff = (size_t)l * NN;

    for (int k0 = 0; k0 < KTOT; k0 += 8) {
        int k = k0 + lak;
        const float* src = (k < DIN) ? (g_x + (size_t)k * LN + xoff)
                                     : (g_gh + (size_t)(k - DIN) * NN);
        float4 av = *(const float4*)(src + m0 + lam);
        *(float4*)&As[lak][lam] = av;
        float2 bv = *(const float2*)(g_W + (size_t)(k0 + lbk) * GATES + c0 + lbc);
        *(float2*)&Bs[lbk][lbc] = bv;
        __syncthreads();

        unsigned a[2][4], b[4][2];
        #pragma unroll
        for (int mi = 0; mi < 2; mi++) {
            int mr = wm + mi * 16 + gid;
            a[mi][0] = __float_as_uint(As[tig    ][mr    ]);
            a[mi][1] = __float_as_uint(As[tig    ][mr + 8]);
            a[mi][2] = __float_as_uint(As[tig + 4][mr    ]);
            a[mi][3] = __float_as_uint(As[tig + 4][mr + 8]);
        }
        #pragma unroll
        for (int ni = 0; ni < 4; ni++) {
            int nc = wn + ni * 8 + gid;
            b[ni][0] = __float_as_uint(Bs[tig    ][nc]);
            b[ni][1] = __float_as_uint(Bs[tig + 4][nc]);
        }
        #pragma unroll
        for (int mi = 0; mi < 2; mi++)
            #pragma unroll
            for (int ni = 0; ni < 4; ni++) {
                asm volatile(
                    "mma.sync.aligned.m16n8k8.row.col.f32.tf32.tf32.f32 "
                    "{%0,%1,%2,%3}, {%4,%5,%6,%7}, {%8,%9}, {%0,%1,%2,%3};"
                    : "+f"(acc[mi][ni][0]), "+f"(acc[mi][ni][1]),
                      "+f"(acc[mi][ni][2]), "+f"(acc[mi][ni][3])
                    : "r"(a[mi][0]), "r"(a[mi][1]), "r"(a[mi][2]), "r"(a[mi][3]),
                      "r"(b[ni][0]), "r"(b[ni][1]));
            }
        __syncthreads();
    }

    // epilogue: D[m][c] -> g_gates[c][m] (+cbias)
    #pragma unroll
    for (int mi = 0; mi < 2; mi++) {
        int m = m0 + wm + mi * 16 + gid;
        #pragma unroll
        for (int ni = 0; ni < 4; ni++) {
            int c = c0 + wn + ni * 8 + 2 * tig;
            float cb0 = __ldg(&g_cbias[c]);
            float cb1 = __ldg(&g_cbias[c + 1]);
            g_gates[(size_t)c       * NN + m    ] = acc[mi][ni][0] + cb0;
            g_gates[(size_t)(c + 1) * NN + m    ] = acc[mi][ni][1] + cb1;
            g_gates[(size_t)c       * NN + m + 8] = acc[mi][ni][2] + cb0;
            g_gates[(size_t)(c + 1) * NN + m + 8] = acc[mi][ni][3] + cb1;
        }
    }
}

// ---------------- LSTM cell elementwise ----------------
__global__ void cell_kernel() {
    size_t i = (size_t)blockIdx.x * blockDim.x + threadIdx.x;
    float iv = g_gates[i];
    float fv = g_gates[i + (size_t)128 * NN];
    float gv = g_gates[i + (size_t)256 * NN];
    float ov = g_gates[i + (size_t)384 * NN];
    float gc = g_gc[i];
    float cn = sigf(fv) * gc + sigf(iv) * tanhf(gv);
    g_c[i] = cn;
    g_h[i] = sigf(ov) * tanhf(cn);
}

// ---------------- head MLP ----------------
__global__ void head_kernel(const float* __restrict__ W1, const float* __restrict__ b1,
                            const float* __restrict__ W2, const float* __restrict__ b2,
                            float* __restrict__ out, int rows)
{
    __shared__ float sW1[20 * 128];
    __shared__ float sb1[20], sW2[20];
    __shared__ float sb2;
    int tid = threadIdx.x;
    for (int i = tid; i < 20 * 128; i += 256) sW1[i] = W1[i];
    if (tid < 20) { sb1[tid] = b1[tid]; sW2[tid] = W2[tid]; }
    if (tid == 0) sb2 = b2[0];
    __syncthreads();
    int b = blockIdx.x * 256 + tid;
    if (b >= rows) return;
    float z1[20];
    #pragma unroll
    for (int j = 0; j < 20; j++) z1[j] = sb1[j];
    for (int k = 0; k < 128; k++) {
        float hv = g_h[(size_t)k * NN + b];
        #pragma unroll
        for (int j = 0; j < 20; j++) z1[j] += hv * sW1[j * 128 + k];
    }
    float z = sb2;
    #pragma unroll
    for (int j = 0; j < 20; j++) z += z1[j] * sW2[j];
    out[b] = 1.0f / (1.0f + expf(-z));
}

// ---------------- launch ----------------
extern "C" void kernel_launch(void* const* d_in, const int* in_sizes, int n_in,
                              void* d_out, int out_size)
{
    const float* op    = (const float*)d_in[0];
    const float* attr  = (const float*)d_in[1];
    const float* filt  = (const float*)d_in[2];
    const float* outp  = (const float*)d_in[3];
    const int*   mapping = (const int*)d_in[4];
    int wb = (in_sizes[5] == 1) ? 6 : 5;
    const float* Wf    = (const float*)d_in[wb + 0];
    const float* bf    = (const float*)d_in[wb + 1];
    const float* Wo    = (const float*)d_in[wb + 2];
    const float* bo    = (const float*)d_in[wb + 3];
    const float* g1    = (const float*)d_in[wb + 4];
    const float* beta1 = (const float*)d_in[wb + 5];
    const float* g2    = (const float*)d_in[wb + 6];
    const float* beta2 = (const float*)d_in[wb + 7];
    const float* Wih   = (const float*)d_in[wb + 8];
    const float* Whh   = (const float*)d_in[wb + 9];
    const float* bih   = (const float*)d_in[wb + 10];
    const float* bhh   = (const float*)d_in[wb + 11];
    const float* W1    = (const float*)d_in[wb + 12];
    const float* b1    = (const float*)d_in[wb + 13];
    const float* W2    = (const float*)d_in[wb + 14];
    const float* b2    = (const float*)d_in[wb + 15];
    float* outptr = (float*)d_out;

    zero_kernel<<<(2 * HD * NN) / 256, 256>>>();
    build_x_kernel<<<LN / 256, 256>>>(op, attr, filt, outp, Wf, bf, Wo, bo);
    stats_kernel<<<dim3(64, 12), 256>>>();
    round_x_kernel<<<(64 * LN) / 256, 256>>>();
    fold_kernel<<<1, 64>>>(g1, beta1, g2, beta2);
    cbias_kernel<<<1, 512>>>(Wih, bih, bhh);
    weight_kernel<<<KTOT, 512>>>(Wih, Whh);

    for (int t = 0; t < L_STEPS; t++) {
        int l = L_STEPS - 1 - t;
        gather_kernel<<<dim3(NN / 256, HD), 256>>>(mapping, l);
        gates_gemm_tc<<<dim3(NN / 128, GATES / 64), 256>>>(l);
        cell_kernel<<<(HD * NN) / 256, 256>>>();
    }

    head_kernel<<<(out_size + 255) / 256, 256>>>(W1, b1, W2, b2, outptr, out_size);
}

// round 3
// speedup vs baseline: 1.8812x; 1.1592x over previous
#include <cuda_runtime.h>
#include <math.h>

#define L_STEPS 24
#define NN 16384
#define LN (24*16384)          // 393216
#define HD 128
#define HD2 136                // gh rows padded (8 zero rows)
#define DIN 136
#define KTOT 264
#define KPAD 272               // padded K (17 chunks of 16)
#define GATES 512

// ---------------- device scratch (feature-major layouts) ----------------
__device__ __align__(128) float g_x[(size_t)DIN * LN];      // [k][LN] tf32-rounded
__device__ __align__(128) float g_W[(size_t)KPAD * GATES];  // [k][col], col = d*4+gate, tf32
__device__ __align__(128) float g_cbias[GATES];             // [col]
__device__ __align__(128) float g_stats[128];
__device__ __align__(128) float g_ss[64], g_st[64];
__device__ __align__(128) float g_gh[(size_t)HD2 * NN];     // [d][N], rows 128..135 zero
__device__ __align__(128) float g_gc[(size_t)HD * NN];
__device__ __align__(128) float g_h[(size_t)HD * NN];
__device__ __align__(128) float g_c[(size_t)HD * NN];

__device__ __forceinline__ float sigf(float x) { return 1.0f / (1.0f + expf(-x)); }
__device__ __forceinline__ float tf32r(float x) {
    float y; asm("cvt.rna.tf32.f32 %0, %1;" : "=f"(y) : "f"(x)); return y;
}

// ---------------- zero init: h, c, gh pad rows, stats ----------------
__global__ void zero_kernel() {
    size_t i = (size_t)blockIdx.x * blockDim.x + threadIdx.x;
    size_t hn = (size_t)HD * NN;
    if (i < hn)            g_h[i] = 0.0f;
    else if (i < 2 * hn)   g_c[i - hn] = 0.0f;
    else                   g_gh[(size_t)HD * NN + (i - 2 * hn)] = 0.0f;  // pad rows
    if (i < 128) g_stats[i] = 0.0f;
}

// ---------------- build lstm_in columns (tf32-rounded at store) ----------------
__global__ __launch_bounds__(256) void build_x_kernel(
    const float* __restrict__ op, const float* __restrict__ attr,
    const float* __restrict__ filt, const float* __restrict__ outp,
    const float* __restrict__ Wf, const float* __restrict__ bf,
    const float* __restrict__ Wo, const float* __restrict__ bo)
{
    __shared__ __align__(16) float sWfT[74 * 32];
    __shared__ __align__(16) float sWoT[32 * 32];
    __shared__ float sbf[32], sbo[32];
    int tid = threadIdx.x;
    for (int i = tid; i < 74 * 32; i += 256) { int j = i / 74, k = i % 74; sWfT[k * 32 + j] = Wf[i]; }
    for (int i = tid; i < 32 * 32; i += 256) { int j = i / 32, k = i % 32; sWoT[k * 32 + j] = Wo[i]; }
    if (tid < 32) { sbf[tid] = bf[tid]; sbo[tid] = bo[tid]; }
    __syncthreads();

    size_t r = (size_t)blockIdx.x * 256 + tid;

    const float* opr = op + r * 16;
    #pragma unroll
    for (int k = 0; k < 16; k++) g_x[(size_t)k * LN + r] = tf32r(opr[k]);
    const float* atr = attr + r * 56;
    #pragma unroll 8
    for (int k = 0; k < 56; k++) g_x[(size_t)(16 + k) * LN + r] = tf32r(atr[k]);

    float acc[32];
    #pragma unroll
    for (int j = 0; j < 32; j++) acc[j] = sbf[j];
    const float* frow = filt + r * 74;
    for (int k = 0; k < 74; k++) {
        float fv = __ldg(&frow[k]);
        const float4* wrow = (const float4*)&sWfT[k * 32];
        #pragma unroll
        for (int j4 = 0; j4 < 8; j4++) {
            float4 w = wrow[j4];
            acc[j4*4+0] += fv * w.x; acc[j4*4+1] += fv * w.y;
            acc[j4*4+2] += fv * w.z; acc[j4*4+3] += fv * w.w;
        }
    }
    #pragma unroll
    for (int j = 0; j < 32; j++) {
        float v = acc[j]; v = v > 0.0f ? v : 0.01f * v;
        g_x[(size_t)(72 + j) * LN + r] = tf32r(v);
    }
    #pragma unroll
    for (int j = 0; j < 32; j++) acc[j] = sbo[j];
    const float* orow = outp + r * 32;
    for (int k = 0; k < 32; k++) {
        float ov = __ldg(&orow[k]);
        const float4* wrow = (const float4*)&sWoT[k * 32];
        #pragma unroll
        for (int j4 = 0; j4 < 8; j4++) {
            float4 w = wrow[j4];
            acc[j4*4+0] += ov * w.x; acc[j4*4+1] += ov * w.y;
            acc[j4*4+2] += ov * w.z; acc[j4*4+3] += ov * w.w;
        }
    }
    #pragma unroll
    for (int j = 0; j < 32; j++) {
        float v = acc[j]; v = v > 0.0f ? v : 0.01f * v;
        g_x[(size_t)(104 + j) * LN + r] = tf32r(v);
    }
}

// ---------------- BN stats over (rounded) columns 72..135 ----------------
__global__ void stats_kernel() {
    int f = blockIdx.x;
    size_t col = (size_t)(72 + f) * LN;
    float s = 0.0f, q = 0.0f;
    for (size_t i = (size_t)blockIdx.y * blockDim.x + threadIdx.x; i < LN;
         i += (size_t)gridDim.y * blockDim.x) {
        float v = g_x[col + i];
        s += v; q += v * v;
    }
    for (int o = 16; o > 0; o >>= 1) {
        s += __shfl_down_sync(0xffffffffu, s, o);
        q += __shfl_down_sync(0xffffffffu, q, o);
    }
    __shared__ float shs[8], shq[8];
    int lane = threadIdx.x & 31, w = threadIdx.x >> 5;
    if (lane == 0) { shs[w] = s; shq[w] = q; }
    __syncthreads();
    if (threadIdx.x == 0) {
        float ts = 0.0f, tq = 0.0f;
        for (int i = 0; i < 8; i++) { ts += shs[i]; tq += shq[i]; }
        atomicAdd(&g_stats[f], ts);
        atomicAdd(&g_stats[64 + f], tq);
    }
}

// ---------------- BN fold scale/shift ----------------
__global__ void fold_kernel(
    const float* __restrict__ g1, const float* __restrict__ beta1,
    const float* __restrict__ g2, const float* __restrict__ beta2)
{
    int tid = threadIdx.x;   // 64
    float mean = g_stats[tid] * (1.0f / (float)LN);
    float var  = g_stats[64 + tid] * (1.0f / (float)LN) - mean * mean;
    float gg = tid < 32 ? g1[tid] : g2[tid - 32];
    float bb = tid < 32 ? beta1[tid] : beta2[tid - 32];
    float sc = gg * rsqrtf(var + 1e-5f);
    g_ss[tid] = sc;
    g_st[tid] = bb - mean * sc;
}

// ---------------- combined bias in interleaved col order ----------------
__global__ void cbias_kernel(
    const float* __restrict__ Wih,
    const float* __restrict__ bih, const float* __restrict__ bhh)
{
    int col = threadIdx.x;              // 512; col = d*4 + gate
    int gate = col & 3, d = col >> 2;
    int c = gate * 128 + d;             // original row index
    const float* wr = Wih + (size_t)c * DIN;
    float cb = bih[c] + bhh[c];
    #pragma unroll
    for (int j = 0; j < 32; j++) cb += g_st[j] * wr[72 + j];
    #pragma unroll
    for (int j = 0; j < 32; j++) cb += g_st[32 + j] * wr[104 + j];
    g_cbias[col] = cb;
}

// ---------------- weight matrix build: [k][col], tf32, K padded ----------------
__global__ void weight_kernel(const float* __restrict__ Wih, const float* __restrict__ Whh) {
    int k = blockIdx.x;                 // 0..271
    int col = threadIdx.x;              // 512
    int gate = col & 3, d = col >> 2;
    int c = gate * 128 + d;
    float w;
    if (k < 72)        w = Wih[(size_t)c * DIN + k];
    else if (k < 104)  w = Wih[(size_t)c * DIN + k] * g_ss[k - 72];
    else if (k < 136)  w = Wih[(size_t)c * DIN + k] * g_ss[32 + (k - 104)];
    else if (k < 264)  w = Whh[(size_t)c * HD + (k - 136)];
    else               w = 0.0f;
    g_W[(size_t)k * GATES + col] = tf32r(w);
}

// ---------------- per-step neighbor gather ----------------
__global__ void gather_kernel(const int* __restrict__ mapping, int l) {
    int n = blockIdx.x * blockDim.x + threadIdx.x;
    int d = blockIdx.y;
    const int* mp = mapping + ((size_t)l * NN + n) * 2;
    int m0 = __ldg(&mp[0]), m1 = __ldg(&mp[1]);
    size_t base = (size_t)d * NN;
    float gh = 0.0f, gc = 0.0f;
    if (m0 > 0) { gh += g_h[base + m0 - 1]; gc += g_c[base + m0 - 1]; }
    if (m1 > 0) { gh += g_h[base + m1 - 1]; gc += g_c[base + m1 - 1]; }
    g_gh[base + n] = tf32r(0.5f * gh);
    g_gc[base + n] = 0.5f * gc;
}

// ---------------- fused gates GEMM + LSTM cell ----------------
// M=16384 (BM=128), cols=512 (BN=128, interleaved d*4+gate), K=272 (BK=16).
// 256 threads = 8 warps (4m x 2n), warp tile 32m x 64n via m16n8k8 tf32.
#define SSTR 136
__global__ __launch_bounds__(256) void step_kernel(int l) {
    __shared__ __align__(16) float As[16][SSTR];
    __shared__ __align__(16) float Bs[16][SSTR];
    int tid = threadIdx.x;
    int wid = tid >> 5, lane = tid & 31;
    int gid = lane >> 2, tig = lane & 3;
    int m0 = blockIdx.x * 128;
    int cb0 = blockIdx.y * 128;
    int wm = (wid & 3) * 32;
    int wn = (wid >> 2) * 64;

    float acc[2][8][4];
    #pragma unroll
    for (int mi = 0; mi < 2; mi++)
        #pragma unroll
        for (int ni = 0; ni < 8; ni++)
            #pragma unroll
            for (int r = 0; r < 4; r++) acc[mi][ni][r] = 0.0f;

    int arow = tid >> 5;          // 0..7
    int acol = (tid & 31) * 4;    // 0..124
    size_t xoff = (size_t)l * NN;

    for (int k0 = 0; k0 < KPAD; k0 += 16) {
        // register staging (global loads)
        float4 a0v, a1v, b0v, b1v;
        {
            int k = k0 + arow;
            const float* s = (k < DIN) ? g_x + (size_t)k * LN + xoff + m0
                                       : g_gh + (size_t)(k - DIN) * NN + m0;
            a0v = *(const float4*)(s + acol);
            int k2 = k + 8;
            const float* s2 = (k2 < DIN) ? g_x + (size_t)k2 * LN + xoff + m0
                                         : g_gh + (size_t)(k2 - DIN) * NN + m0;
            a1v = *(const float4*)(s2 + acol);
            b0v = *(const float4*)(g_W + (size_t)(k0 + arow) * GATES + cb0 + acol);
            b1v = *(const float4*)(g_W + (size_t)(k0 + arow + 8) * GATES + cb0 + acol);
        }
        __syncthreads();          // previous chunk's MMA reads complete
        *(float4*)&As[arow][acol]     = a0v;
        *(float4*)&As[arow + 8][acol] = a1v;
        *(float4*)&Bs[arow][acol]     = b0v;
        *(float4*)&Bs[arow + 8][acol] = b1v;
        __syncthreads();

        #pragma unroll
        for (int s8 = 0; s8 < 2; s8++) {
            int kb = s8 * 8;
            unsigned a[2][4];
            #pragma unroll
            for (int mi = 0; mi < 2; mi++) {
                int mr = wm + mi * 16 + gid;
                a[mi][0] = __float_as_uint(As[kb + tig    ][mr    ]);
                a[mi][1] = __float_as_uint(As[kb + tig    ][mr + 8]);
                a[mi][2] = __float_as_uint(As[kb + tig + 4][mr    ]);
                a[mi][3] = __float_as_uint(As[kb + tig + 4][mr + 8]);
            }
            #pragma unroll
            for (int ni = 0; ni < 8; ni++) {
                int nc = wn + ni * 8 + gid;
                unsigned b0 = __float_as_uint(Bs[kb + tig    ][nc]);
                unsigned b1 = __float_as_uint(Bs[kb + tig + 4][nc]);
                #pragma unroll
                for (int mi = 0; mi < 2; mi++) {
                    asm volatile(
                        "mma.sync.aligned.m16n8k8.row.col.f32.tf32.tf32.f32 "
                        "{%0,%1,%2,%3}, {%4,%5,%6,%7}, {%8,%9}, {%0,%1,%2,%3};"
                        : "+f"(acc[mi][ni][0]), "+f"(acc[mi][ni][1]),
                          "+f"(acc[mi][ni][2]), "+f"(acc[mi][ni][3])
                        : "r"(a[mi][0]), "r"(a[mi][1]), "r"(a[mi][2]), "r"(a[mi][3]),
                          "r"(b0), "r"(b1));
                }
            }
        }
    }

    // ---- fused cell epilogue ----
    // col c holds (d = c>>2, gate = c&3); even tig lanes own (i,f), odd own (g,o).
    #pragma unroll
    for (int mi = 0; mi < 2; mi++) {
        int r0 = m0 + wm + mi * 16 + gid;
        #pragma unroll
        for (int ni = 0; ni < 8; ni++) {
            int c = cb0 + wn + ni * 8 + 2 * tig;
            float cbv0 = __ldg(&g_cbias[c]);
            float cbv1 = __ldg(&g_cbias[c + 1]);
            float v0 = acc[mi][ni][0] + cbv0;
            float v1 = acc[mi][ni][1] + cbv1;
            float v2 = acc[mi][ni][2] + cbv0;
            float v3 = acc[mi][ni][3] + cbv1;
            float p0 = __shfl_xor_sync(0xffffffffu, v0, 1);
            float p1 = __shfl_xor_sync(0xffffffffu, v1, 1);
            float p2 = __shfl_xor_sync(0xffffffffu, v2, 1);
            float p3 = __shfl_xor_sync(0xffffffffu, v3, 1);
            int d = c >> 2;
            int row; float iv, fv, gv, ov;
            if ((tig & 1) == 0) { row = r0;     iv = v0; fv = v1; gv = p0; ov = p1; }
            else                { row = r0 + 8; iv = p2; fv = p3; gv = v2; ov = v3; }
            float gc = g_gc[(size_t)d * NN + row];
            float cn = sigf(fv) * gc + sigf(iv) * tanhf(gv);
            g_c[(size_t)d * NN + row] = cn;
            g_h[(size_t)d * NN + row] = sigf(ov) * tanhf(cn);
        }
    }
}

// ---------------- head MLP ----------------
__global__ void head_kernel(const float* __restrict__ W1, const float* __restrict__ b1,
                            const float* __restrict__ W2, const float* __restrict__ b2,
                            float* __restrict__ out, int rows)
{
    __shared__ float sW1[20 * 128];
    __shared__ float sb1[20], sW2[20];
    __shared__ float sb2;
    int tid = threadIdx.x;
    for (int i = tid; i < 20 * 128; i += 256) sW1[i] = W1[i];
    if (tid < 20) { sb1[tid] = b1[tid]; sW2[tid] = W2[tid]; }
    if (tid == 0) sb2 = b2[0];
    __syncthreads();
    int b = blockIdx.x * 256 + tid;
    if (b >= rows) return;
    float z1[20];
    #pragma unroll
    for (int j = 0; j < 20; j++) z1[j] = sb1[j];
    for (int k = 0; k < 128; k++) {
        float hv = g_h[(size_t)k * NN + b];
        #pragma unroll
        for (int j = 0; j < 20; j++) z1[j] += hv * sW1[j * 128 + k];
    }
    float z = sb2;
    #pragma unroll
    for (int j = 0; j < 20; j++) z += z1[j] * sW2[j];
    out[b] = 1.0f / (1.0f + expf(-z));
}

// ---------------- launch ----------------
extern "C" void kernel_launch(void* const* d_in, const int* in_sizes, int n_in,
                              void* d_out, int out_size)
{
    const float* op    = (const float*)d_in[0];
    const float* attr  = (const float*)d_in[1];
    const float* filt  = (const float*)d_in[2];
    const float* outp  = (const float*)d_in[3];
    const int*   mapping = (const int*)d_in[4];
    int wb = (in_sizes[5] == 1) ? 6 : 5;
    const float* Wf    = (const float*)d_in[wb + 0];
    const float* bf    = (const float*)d_in[wb + 1];
    const float* Wo    = (const float*)d_in[wb + 2];
    const float* bo    = (const float*)d_in[wb + 3];
    const float* g1    = (const float*)d_in[wb + 4];
    const float* beta1 = (const float*)d_in[wb + 5];
    const float* g2    = (const float*)d_in[wb + 6];
    const float* beta2 = (const float*)d_in[wb + 7];
    const float* Wih   = (const float*)d_in[wb + 8];
    const float* Whh   = (const float*)d_in[wb + 9];
    const float* bih   = (const float*)d_in[wb + 10];
    const float* bhh   = (const float*)d_in[wb + 11];
    const float* W1    = (const float*)d_in[wb + 12];
    const float* b1    = (const float*)d_in[wb + 13];
    const float* W2    = (const float*)d_in[wb + 14];
    const float* b2    = (const float*)d_in[wb + 15];
    float* outptr = (float*)d_out;

    size_t ztotal = 2 * (size_t)HD * NN + 8 * (size_t)NN;
    zero_kernel<<<(int)((ztotal + 255) / 256), 256>>>();
    build_x_kernel<<<LN / 256, 256>>>(op, attr, filt, outp, Wf, bf, Wo, bo);
    stats_kernel<<<dim3(64, 12), 256>>>();
    fold_kernel<<<1, 64>>>(g1, beta1, g2, beta2);
    cbias_kernel<<<1, 512>>>(Wih, bih, bhh);
    weight_kernel<<<KPAD, 512>>>(Wih, Whh);

    for (int t = 0; t < L_STEPS; t++) {
        int l = L_STEPS - 1 - t;
        gather_kernel<<<dim3(NN / 256, HD), 256>>>(mapping, l);
        step_kernel<<<dim3(NN / 128, GATES / 128), 256>>>(l);
    }

    head_kernel<<<(out_size + 255) / 256, 256>>>(W1, b1, W2, b2, outptr, out_size);
}

// round 4
// speedup vs baseline: 1.9401x; 1.0313x over previous
#include <cuda_runtime.h>
#include <math.h>

#define L_STEPS 24
#define NN 16384
#define LN (24*16384)          // 393216
#define HD 128
#define HD2 136                // gh rows padded (8 zero rows)
#define DIN 136
#define KTOT 264
#define KPAD 272               // padded K (17 chunks of 16)
#define GATES 512

// ---------------- device scratch (feature-major layouts) ----------------
__device__ __align__(128) float g_x[(size_t)DIN * LN];      // [k][LN]
__device__ __align__(128) float g_W[(size_t)KPAD * GATES];  // [k][col], col = d*4+gate
__device__ __align__(128) float g_cbias[GATES];             // [col]
__device__ __align__(128) float g_stats[128];
__device__ __align__(128) float g_ss[64], g_st[64];
__device__ __align__(128) float g_gh[(size_t)HD2 * NN];     // [d][N], rows 128..135 zero
__device__ __align__(128) float g_gc[(size_t)HD * NN];
__device__ __align__(128) float g_h[(size_t)HD * NN];
__device__ __align__(128) float g_c[(size_t)HD * NN];

__device__ __forceinline__ float sigf(float x) { return 1.0f / (1.0f + expf(-x)); }
// pack two fp32 into bf16x2 (lo in low half, hi in high half)
__device__ __forceinline__ unsigned pk(float lo, float hi) {
    unsigned r; asm("cvt.rn.bf16x2.f32 %0, %1, %2;" : "=r"(r) : "f"(hi), "f"(lo)); return r;
}

// ---------------- zero init: h, c, gh pad rows, stats ----------------
__global__ void zero_kernel() {
    size_t i = (size_t)blockIdx.x * blockDim.x + threadIdx.x;
    size_t hn = (size_t)HD * NN;
    if (i < hn)            g_h[i] = 0.0f;
    else if (i < 2 * hn)   g_c[i - hn] = 0.0f;
    else                   g_gh[(size_t)HD * NN + (i - 2 * hn)] = 0.0f;
    if (i < 128) g_stats[i] = 0.0f;
}

// ---------------- build lstm_in columns ----------------
__global__ __launch_bounds__(256) void build_x_kernel(
    const float* __restrict__ op, const float* __restrict__ attr,
    const float* __restrict__ filt, const float* __restrict__ outp,
    const float* __restrict__ Wf, const float* __restrict__ bf,
    const float* __restrict__ Wo, const float* __restrict__ bo)
{
    __shared__ __align__(16) float sWfT[74 * 32];
    __shared__ __align__(16) float sWoT[32 * 32];
    __shared__ float sbf[32], sbo[32];
    int tid = threadIdx.x;
    for (int i = tid; i < 74 * 32; i += 256) { int j = i / 74, k = i % 74; sWfT[k * 32 + j] = Wf[i]; }
    for (int i = tid; i < 32 * 32; i += 256) { int j = i / 32, k = i % 32; sWoT[k * 32 + j] = Wo[i]; }
    if (tid < 32) { sbf[tid] = bf[tid]; sbo[tid] = bo[tid]; }
    __syncthreads();

    size_t r = (size_t)blockIdx.x * 256 + tid;

    const float* opr = op + r * 16;
    #pragma unroll
    for (int k = 0; k < 16; k++) g_x[(size_t)k * LN + r] = opr[k];
    const float* atr = attr + r * 56;
    #pragma unroll 8
    for (int k = 0; k < 56; k++) g_x[(size_t)(16 + k) * LN + r] = atr[k];

    float acc[32];
    #pragma unroll
    for (int j = 0; j < 32; j++) acc[j] = sbf[j];
    const float* frow = filt + r * 74;
    for (int k = 0; k < 74; k++) {
        float fv = __ldg(&frow[k]);
        const float4* wrow = (const float4*)&sWfT[k * 32];
        #pragma unroll
        for (int j4 = 0; j4 < 8; j4++) {
            float4 w = wrow[j4];
            acc[j4*4+0] += fv * w.x; acc[j4*4+1] += fv * w.y;
            acc[j4*4+2] += fv * w.z; acc[j4*4+3] += fv * w.w;
        }
    }
    #pragma unroll
    for (int j = 0; j < 32; j++) {
        float v = acc[j]; v = v > 0.0f ? v : 0.01f * v;
        g_x[(size_t)(72 + j) * LN + r] = v;
    }
    #pragma unroll
    for (int j = 0; j < 32; j++) acc[j] = sbo[j];
    const float* orow = outp + r * 32;
    for (int k = 0; k < 32; k++) {
        float ov = __ldg(&orow[k]);
        const float4* wrow = (const float4*)&sWoT[k * 32];
        #pragma unroll
        for (int j4 = 0; j4 < 8; j4++) {
            float4 w = wrow[j4];
            acc[j4*4+0] += ov * w.x; acc[j4*4+1] += ov * w.y;
            acc[j4*4+2] += ov * w.z; acc[j4*4+3] += ov * w.w;
        }
    }
    #pragma unroll
    for (int j = 0; j < 32; j++) {
        float v = acc[j]; v = v > 0.0f ? v : 0.01f * v;
        g_x[(size_t)(104 + j) * LN + r] = v;
    }
}

// ---------------- BN stats over columns 72..135 ----------------
__global__ void stats_kernel() {
    int f = blockIdx.x;
    size_t col = (size_t)(72 + f) * LN;
    float s = 0.0f, q = 0.0f;
    for (size_t i = (size_t)blockIdx.y * blockDim.x + threadIdx.x; i < LN;
         i += (size_t)gridDim.y * blockDim.x) {
        float v = g_x[col + i];
        s += v; q += v * v;
    }
    for (int o = 16; o > 0; o >>= 1) {
        s += __shfl_down_sync(0xffffffffu, s, o);
        q += __shfl_down_sync(0xffffffffu, q, o);
    }
    __shared__ float shs[8], shq[8];
    int lane = threadIdx.x & 31, w = threadIdx.x >> 5;
    if (lane == 0) { shs[w] = s; shq[w] = q; }
    __syncthreads();
    if (threadIdx.x == 0) {
        float ts = 0.0f, tq = 0.0f;
        for (int i = 0; i < 8; i++) { ts += shs[i]; tq += shq[i]; }
        atomicAdd(&g_stats[f], ts);
        atomicAdd(&g_stats[64 + f], tq);
    }
}

// ---------------- BN fold scale/shift ----------------
__global__ void fold_kernel(
    const float* __restrict__ g1, const float* __restrict__ beta1,
    const float* __restrict__ g2, const float* __restrict__ beta2)
{
    int tid = threadIdx.x;   // 64
    float mean = g_stats[tid] * (1.0f / (float)LN);
    float var  = g_stats[64 + tid] * (1.0f / (float)LN) - mean * mean;
    float gg = tid < 32 ? g1[tid] : g2[tid - 32];
    float bb = tid < 32 ? beta1[tid] : beta2[tid - 32];
    float sc = gg * rsqrtf(var + 1e-5f);
    g_ss[tid] = sc;
    g_st[tid] = bb - mean * sc;
}

// ---------------- combined bias in interleaved col order ----------------
__global__ void cbias_kernel(
    const float* __restrict__ Wih,
    const float* __restrict__ bih, const float* __restrict__ bhh)
{
    int col = threadIdx.x;              // 512; col = d*4 + gate
    int gate = col & 3, d = col >> 2;
    int c = gate * 128 + d;
    const float* wr = Wih + (size_t)c * DIN;
    float cb = bih[c] + bhh[c];
    #pragma unroll
    for (int j = 0; j < 32; j++) cb += g_st[j] * wr[72 + j];
    #pragma unroll
    for (int j = 0; j < 32; j++) cb += g_st[32 + j] * wr[104 + j];
    g_cbias[col] = cb;
}

// ---------------- weight matrix build: [k][col], K padded ----------------
__global__ void weight_kernel(const float* __restrict__ Wih, const float* __restrict__ Whh) {
    int k = blockIdx.x;                 // 0..271
    int col = threadIdx.x;              // 512
    int gate = col & 3, d = col >> 2;
    int c = gate * 128 + d;
    float w;
    if (k < 72)        w = Wih[(size_t)c * DIN + k];
    else if (k < 104)  w = Wih[(size_t)c * DIN + k] * g_ss[k - 72];
    else if (k < 136)  w = Wih[(size_t)c * DIN + k] * g_ss[32 + (k - 104)];
    else if (k < 264)  w = Whh[(size_t)c * HD + (k - 136)];
    else               w = 0.0f;
    g_W[(size_t)k * GATES + col] = w;
}

// ---------------- per-step neighbor gather ----------------
__global__ void gather_kernel(const int* __restrict__ mapping, int l) {
    int n = blockIdx.x * blockDim.x + threadIdx.x;
    int d = blockIdx.y;
    const int* mp = mapping + ((size_t)l * NN + n) * 2;
    int m0 = __ldg(&mp[0]), m1 = __ldg(&mp[1]);
    size_t base = (size_t)d * NN;
    float gh = 0.0f, gc = 0.0f;
    if (m0 > 0) { gh += g_h[base + m0 - 1]; gc += g_c[base + m0 - 1]; }
    if (m1 > 0) { gh += g_h[base + m1 - 1]; gc += g_c[base + m1 - 1]; }
    g_gh[base + n] = 0.5f * gh;
    g_gc[base + n] = 0.5f * gc;
}

// ---------------- fused gates GEMM + LSTM cell (bf16 m16n8k16) ----------------
// M=16384 (BM=128), cols=512 (BN=128, interleaved d*4+gate), K=272 (BK=16).
// 256 threads = 8 warps (4m x 2n), warp tile 32m x 64n.
#define SSTR 140
__global__ __launch_bounds__(256) void step_kernel(int l) {
    __shared__ __align__(16) float As[16][SSTR];
    __shared__ __align__(16) float Bs[16][SSTR];
    int tid = threadIdx.x;
    int wid = tid >> 5, lane = tid & 31;
    int gid = lane >> 2, tig = lane & 3;
    int m0 = blockIdx.x * 128;
    int cb0 = blockIdx.y * 128;
    int wm = (wid & 3) * 32;
    int wn = (wid >> 2) * 64;

    float acc[2][8][4];
    #pragma unroll
    for (int mi = 0; mi < 2; mi++)
        #pragma unroll
        for (int ni = 0; ni < 8; ni++)
            #pragma unroll
            for (int r = 0; r < 4; r++) acc[mi][ni][r] = 0.0f;

    int arow = tid >> 5;          // 0..7
    int acol = (tid & 31) * 4;    // 0..124
    size_t xoff = (size_t)l * NN;

    for (int k0 = 0; k0 < KPAD; k0 += 16) {
        float4 a0v, a1v, b0v, b1v;
        {
            int k = k0 + arow;
            const float* s = (k < DIN) ? g_x + (size_t)k * LN + xoff + m0
                                       : g_gh + (size_t)(k - DIN) * NN + m0;
            a0v = *(const float4*)(s + acol);
            int k2 = k + 8;
            const float* s2 = (k2 < DIN) ? g_x + (size_t)k2 * LN + xoff + m0
                                         : g_gh + (size_t)(k2 - DIN) * NN + m0;
            a1v = *(const float4*)(s2 + acol);
            b0v = *(const float4*)(g_W + (size_t)(k0 + arow) * GATES + cb0 + acol);
            b1v = *(const float4*)(g_W + (size_t)(k0 + arow + 8) * GATES + cb0 + acol);
        }
        __syncthreads();
        *(float4*)&As[arow][acol]     = a0v;
        *(float4*)&As[arow + 8][acol] = a1v;
        *(float4*)&Bs[arow][acol]     = b0v;
        *(float4*)&Bs[arow + 8][acol] = b1v;
        __syncthreads();

        // bf16 fragments (k16 per chunk, one MMA depth)
        unsigned a[2][4];
        #pragma unroll
        for (int mi = 0; mi < 2; mi++) {
            int mr = wm + mi * 16 + gid;
            a[mi][0] = pk(As[2*tig    ][mr    ], As[2*tig + 1][mr    ]);
            a[mi][1] = pk(As[2*tig    ][mr + 8], As[2*tig + 1][mr + 8]);
            a[mi][2] = pk(As[2*tig + 8][mr    ], As[2*tig + 9][mr    ]);
            a[mi][3] = pk(As[2*tig + 8][mr + 8], As[2*tig + 9][mr + 8]);
        }
        #pragma unroll
        for (int ni = 0; ni < 8; ni++) {
            int nc = wn + ni * 8 + gid;
            unsigned b0 = pk(Bs[2*tig    ][nc], Bs[2*tig + 1][nc]);
            unsigned b1 = pk(Bs[2*tig + 8][nc], Bs[2*tig + 9][nc]);
            #pragma unroll
            for (int mi = 0; mi < 2; mi++) {
                asm volatile(
                    "mma.sync.aligned.m16n8k16.row.col.f32.bf16.bf16.f32 "
                    "{%0,%1,%2,%3}, {%4,%5,%6,%7}, {%8,%9}, {%0,%1,%2,%3};"
                    : "+f"(acc[mi][ni][0]), "+f"(acc[mi][ni][1]),
                      "+f"(acc[mi][ni][2]), "+f"(acc[mi][ni][3])
                    : "r"(a[mi][0]), "r"(a[mi][1]), "r"(a[mi][2]), "r"(a[mi][3]),
                      "r"(b0), "r"(b1));
            }
        }
    }

    // ---- fused cell epilogue ----
    #pragma unroll
    for (int mi = 0; mi < 2; mi++) {
        int r0 = m0 + wm + mi * 16 + gid;
        #pragma unroll
        for (int ni = 0; ni < 8; ni++) {
            int c = cb0 + wn + ni * 8 + 2 * tig;
            float cbv0 = __ldg(&g_cbias[c]);
            float cbv1 = __ldg(&g_cbias[c + 1]);
            float v0 = acc[mi][ni][0] + cbv0;
            float v1 = acc[mi][ni][1] + cbv1;
            float v2 = acc[mi][ni][2] + cbv0;
            float v3 = acc[mi][ni][3] + cbv1;
            float p0 = __shfl_xor_sync(0xffffffffu, v0, 1);
            float p1 = __shfl_xor_sync(0xffffffffu, v1, 1);
            float p2 = __shfl_xor_sync(0xffffffffu, v2, 1);
            float p3 = __shfl_xor_sync(0xffffffffu, v3, 1);
            int d = c >> 2;
            int row; float iv, fv, gv, ov;
            if ((tig & 1) == 0) { row = r0;     iv = v0; fv = v1; gv = p0; ov = p1; }
            else                { row = r0 + 8; iv = p2; fv = p3; gv = v2; ov = v3; }
            float gc = g_gc[(size_t)d * NN + row];
            float cn = sigf(fv) * gc + sigf(iv) * tanhf(gv);
            g_c[(size_t)d * NN + row] = cn;
            g_h[(size_t)d * NN + row] = sigf(ov) * tanhf(cn);
        }
    }
}

// ---------------- head MLP ----------------
__global__ void head_kernel(const float* __restrict__ W1, const float* __restrict__ b1,
                            const float* __restrict__ W2, const float* __restrict__ b2,
                            float* __restrict__ out, int rows)
{
    __shared__ float sW1[20 * 128];
    __shared__ float sb1[20], sW2[20];
    __shared__ float sb2;
    int tid = threadIdx.x;
    for (int i = tid; i < 20 * 128; i += 256) sW1[i] = W1[i];
    if (tid < 20) { sb1[tid] = b1[tid]; sW2[tid] = W2[tid]; }
    if (tid == 0) sb2 = b2[0];
    __syncthreads();
    int b = blockIdx.x * 256 + tid;
    if (b >= rows) return;
    float z1[20];
    #pragma unroll
    for (int j = 0; j < 20; j++) z1[j] = sb1[j];
    for (int k = 0; k < 128; k++) {
        float hv = g_h[(size_t)k * NN + b];
        #pragma unroll
        for (int j = 0; j < 20; j++) z1[j] += hv * sW1[j * 128 + k];
    }
    float z = sb2;
    #pragma unroll
    for (int j = 0; j < 20; j++) z += z1[j] * sW2[j];
    out[b] = 1.0f / (1.0f + expf(-z));
}

// ---------------- launch ----------------
extern "C" void kernel_launch(void* const* d_in, const int* in_sizes, int n_in,
                              void* d_out, int out_size)
{
    const float* op    = (const float*)d_in[0];
    const float* attr  = (const float*)d_in[1];
    const float* filt  = (const float*)d_in[2];
    const float* outp  = (const float*)d_in[3];
    const int*   mapping = (const int*)d_in[4];
    int wb = (in_sizes[5] == 1) ? 6 : 5;
    const float* Wf    = (const float*)d_in[wb + 0];
    const float* bf    = (const float*)d_in[wb + 1];
    const float* Wo    = (const float*)d_in[wb + 2];
    const float* bo    = (const float*)d_in[wb + 3];
    const float* g1    = (const float*)d_in[wb + 4];
    const float* beta1 = (const float*)d_in[wb + 5];
    const float* g2    = (const float*)d_in[wb + 6];
    const float* beta2 = (const float*)d_in[wb + 7];
    const float* Wih   = (const float*)d_in[wb + 8];
    const float* Whh   = (const float*)d_in[wb + 9];
    const float* bih   = (const float*)d_in[wb + 10];
    const float* bhh   = (const float*)d_in[wb + 11];
    const float* W1    = (const float*)d_in[wb + 12];
    const float* b1    = (const float*)d_in[wb + 13];
    const float* W2    = (const float*)d_in[wb + 14];
    const float* b2    = (const float*)d_in[wb + 15];
    float* outptr = (float*)d_out;

    size_t ztotal = 2 * (size_t)HD * NN + 8 * (size_t)NN;
    zero_kernel<<<(int)((ztotal + 255) / 256), 256>>>();
    build_x_kernel<<<LN / 256, 256>>>(op, attr, filt, outp, Wf, bf, Wo, bo);
    stats_kernel<<<dim3(64, 12), 256>>>();
    fold_kernel<<<1, 64>>>(g1, beta1, g2, beta2);
    cbias_kernel<<<1, 512>>>(Wih, bih, bhh);
    weight_kernel<<<KPAD, 512>>>(Wih, Whh);

    for (int t = 0; t < L_STEPS; t++) {
        int l = L_STEPS - 1 - t;
        gather_kernel<<<dim3(NN / 256, HD), 256>>>(mapping, l);
        step_kernel<<<dim3(NN / 128, GATES / 128), 256>>>(l);
    }

    head_kernel<<<(out_size + 255) / 256, 256>>>(W1, b1, W2, b2, outptr, out_size);
}

// round 5
// speedup vs baseline: 2.3357x; 1.2039x over previous
#include <cuda_runtime.h>
#include <math.h>

#define L_STEPS 24
#define NN 16384
#define LN (24*16384)          // 393216
#define HD 128
#define HP 136                 // padded node-major row pitch (floats)
#define DIN 136
#define KPAD 272               // padded K (17 chunks of 16)
#define GATES 512
#define SSTR 140

// ---------------- device scratch ----------------
__device__ __align__(128) float g_x[(size_t)DIN * LN];      // [k][LN] feature-major
__device__ __align__(128) float g_W[(size_t)KPAD * GATES];  // [k][col], col = d*4+gate
__device__ __align__(128) float g_cbias[GATES];
__device__ __align__(128) float g_stats[128];
__device__ __align__(128) float g_ss[64], g_st[64];
__device__ __align__(128) float g_h[(size_t)NN * HP];       // [n][136], cols 128..135 zero
__device__ __align__(128) float g_c[(size_t)NN * HD];       // [n][128]
__device__ __align__(128) float g_gh[(size_t)NN * HP];      // [n][136], cols 128..135 zero
__device__ __align__(128) float g_gc[(size_t)NN * HD];      // [n][128]

__device__ __forceinline__ float sigf(float x) { return 1.0f / (1.0f + expf(-x)); }
__device__ __forceinline__ unsigned pk(float lo, float hi) {
    unsigned r; asm("cvt.rn.bf16x2.f32 %0, %1, %2;" : "=r"(r) : "f"(hi), "f"(lo)); return r;
}

// ---------------- zero init: h, c, gh (incl pads), stats ----------------
__global__ void zero_kernel() {
    size_t i = (size_t)blockIdx.x * blockDim.x + threadIdx.x;
    size_t hp = (size_t)NN * HP, hd = (size_t)NN * HD;
    if (i < hp)                 g_h[i] = 0.0f;
    else if (i < hp + hd)       g_c[i - hp] = 0.0f;
    else if (i < 2 * hp + hd)   g_gh[i - hp - hd] = 0.0f;
    if (i < 128) g_stats[i] = 0.0f;
}

// ---------------- build lstm_in columns ----------------
__global__ __launch_bounds__(256) void build_x_kernel(
    const float* __restrict__ op, const float* __restrict__ attr,
    const float* __restrict__ filt, const float* __restrict__ outp,
    const float* __restrict__ Wf, const float* __restrict__ bf,
    const float* __restrict__ Wo, const float* __restrict__ bo)
{
    __shared__ __align__(16) float sWfT[74 * 32];
    __shared__ __align__(16) float sWoT[32 * 32];
    __shared__ float sbf[32], sbo[32];
    int tid = threadIdx.x;
    for (int i = tid; i < 74 * 32; i += 256) { int j = i / 74, k = i % 74; sWfT[k * 32 + j] = Wf[i]; }
    for (int i = tid; i < 32 * 32; i += 256) { int j = i / 32, k = i % 32; sWoT[k * 32 + j] = Wo[i]; }
    if (tid < 32) { sbf[tid] = bf[tid]; sbo[tid] = bo[tid]; }
    __syncthreads();

    size_t r = (size_t)blockIdx.x * 256 + tid;

    const float* opr = op + r * 16;
    #pragma unroll
    for (int k = 0; k < 16; k++) g_x[(size_t)k * LN + r] = opr[k];
    const float* atr = attr + r * 56;
    #pragma unroll 8
    for (int k = 0; k < 56; k++) g_x[(size_t)(16 + k) * LN + r] = atr[k];

    float acc[32];
    #pragma unroll
    for (int j = 0; j < 32; j++) acc[j] = sbf[j];
    const float* frow = filt + r * 74;
    for (int k = 0; k < 74; k++) {
        float fv = __ldg(&frow[k]);
        const float4* wrow = (const float4*)&sWfT[k * 32];
        #pragma unroll
        for (int j4 = 0; j4 < 8; j4++) {
            float4 w = wrow[j4];
            acc[j4*4+0] += fv * w.x; acc[j4*4+1] += fv * w.y;
            acc[j4*4+2] += fv * w.z; acc[j4*4+3] += fv * w.w;
        }
    }
    #pragma unroll
    for (int j = 0; j < 32; j++) {
        float v = acc[j]; v = v > 0.0f ? v : 0.01f * v;
        g_x[(size_t)(72 + j) * LN + r] = v;
    }
    #pragma unroll
    for (int j = 0; j < 32; j++) acc[j] = sbo[j];
    const float* orow = outp + r * 32;
    for (int k = 0; k < 32; k++) {
        float ov = __ldg(&orow[k]);
        const float4* wrow = (const float4*)&sWoT[k * 32];
        #pragma unroll
        for (int j4 = 0; j4 < 8; j4++) {
            float4 w = wrow[j4];
            acc[j4*4+0] += ov * w.x; acc[j4*4+1] += ov * w.y;
            acc[j4*4+2] += ov * w.z; acc[j4*4+3] += ov * w.w;
        }
    }
    #pragma unroll
    for (int j = 0; j < 32; j++) {
        float v = acc[j]; v = v > 0.0f ? v : 0.01f * v;
        g_x[(size_t)(104 + j) * LN + r] = v;
    }
}

// ---------------- BN stats over columns 72..135 ----------------
__global__ void stats_kernel() {
    int f = blockIdx.x;
    size_t col = (size_t)(72 + f) * LN;
    float s = 0.0f, q = 0.0f;
    for (size_t i = (size_t)blockIdx.y * blockDim.x + threadIdx.x; i < LN;
         i += (size_t)gridDim.y * blockDim.x) {
        float v = g_x[col + i];
        s += v; q += v * v;
    }
    for (int o = 16; o > 0; o >>= 1) {
        s += __shfl_down_sync(0xffffffffu, s, o);
        q += __shfl_down_sync(0xffffffffu, q, o);
    }
    __shared__ float shs[8], shq[8];
    int lane = threadIdx.x & 31, w = threadIdx.x >> 5;
    if (lane == 0) { shs[w] = s; shq[w] = q; }
    __syncthreads();
    if (threadIdx.x == 0) {
        float ts = 0.0f, tq = 0.0f;
        for (int i = 0; i < 8; i++) { ts += shs[i]; tq += shq[i]; }
        atomicAdd(&g_stats[f], ts);
        atomicAdd(&g_stats[64 + f], tq);
    }
}

// ---------------- BN fold ----------------
__global__ void fold_kernel(
    const float* __restrict__ g1, const float* __restrict__ beta1,
    const float* __restrict__ g2, const float* __restrict__ beta2)
{
    int tid = threadIdx.x;   // 64
    float mean = g_stats[tid] * (1.0f / (float)LN);
    float var  = g_stats[64 + tid] * (1.0f / (float)LN) - mean * mean;
    float gg = tid < 32 ? g1[tid] : g2[tid - 32];
    float bb = tid < 32 ? beta1[tid] : beta2[tid - 32];
    float sc = gg * rsqrtf(var + 1e-5f);
    g_ss[tid] = sc;
    g_st[tid] = bb - mean * sc;
}

// ---------------- combined bias ----------------
__global__ void cbias_kernel(
    const float* __restrict__ Wih,
    const float* __restrict__ bih, const float* __restrict__ bhh)
{
    int col = threadIdx.x;              // 512; col = d*4 + gate
    int gate = col & 3, d = col >> 2;
    int c = gate * 128 + d;
    const float* wr = Wih + (size_t)c * DIN;
    float cb = bih[c] + bhh[c];
    #pragma unroll
    for (int j = 0; j < 32; j++) cb += g_st[j] * wr[72 + j];
    #pragma unroll
    for (int j = 0; j < 32; j++) cb += g_st[32 + j] * wr[104 + j];
    g_cbias[col] = cb;
}

// ---------------- weight matrix build ----------------
__global__ void weight_kernel(const float* __restrict__ Wih, const float* __restrict__ Whh) {
    int k = blockIdx.x;                 // 0..271
    int col = threadIdx.x;              // 512
    int gate = col & 3, d = col >> 2;
    int c = gate * 128 + d;
    float w;
    if (k < 72)        w = Wih[(size_t)c * DIN + k];
    else if (k < 104)  w = Wih[(size_t)c * DIN + k] * g_ss[k - 72];
    else if (k < 136)  w = Wih[(size_t)c * DIN + k] * g_ss[32 + (k - 104)];
    else if (k < 264)  w = Whh[(size_t)c * HD + (k - 136)];
    else               w = 0.0f;
    g_W[(size_t)k * GATES + col] = w;
}

// ---------------- per-step neighbor gather (node-major, coalesced) ----------------
// 8 nodes per 256-thread block; 32 lanes per node read full rows as float4.
__global__ __launch_bounds__(256) void gather_kernel(const int* __restrict__ mapping, int l) {
    int tid = threadIdx.x;
    int node = blockIdx.x * 8 + (tid >> 5);
    int lane = tid & 31;
    const int* mp = mapping + ((size_t)l * NN + node) * 2;
    int m0 = __ldg(&mp[0]), m1 = __ldg(&mp[1]);
    int d4 = lane * 4;
    float4 hs = make_float4(0.f, 0.f, 0.f, 0.f);
    float4 cs = make_float4(0.f, 0.f, 0.f, 0.f);
    if (m0 > 0) {
        float4 a = *(const float4*)(g_h + (size_t)(m0 - 1) * HP + d4);
        float4 b = *(const float4*)(g_c + (size_t)(m0 - 1) * HD + d4);
        hs.x += a.x; hs.y += a.y; hs.z += a.z; hs.w += a.w;
        cs.x += b.x; cs.y += b.y; cs.z += b.z; cs.w += b.w;
    }
    if (m1 > 0) {
        float4 a = *(const float4*)(g_h + (size_t)(m1 - 1) * HP + d4);
        float4 b = *(const float4*)(g_c + (size_t)(m1 - 1) * HD + d4);
        hs.x += a.x; hs.y += a.y; hs.z += a.z; hs.w += a.w;
        cs.x += b.x; cs.y += b.y; cs.z += b.z; cs.w += b.w;
    }
    hs.x *= 0.5f; hs.y *= 0.5f; hs.z *= 0.5f; hs.w *= 0.5f;
    cs.x *= 0.5f; cs.y *= 0.5f; cs.z *= 0.5f; cs.w *= 0.5f;
    *(float4*)(g_gh + (size_t)node * HP + d4) = hs;
    *(float4*)(g_gc + (size_t)node * HD + d4) = cs;
}

// ---------------- fused gates GEMM + LSTM cell (bf16, 2-stage pipeline) ----------------
// M=16384 (BM=128), cols=512 (BN=128), K=272 (BK=16), 8 warps (4m x 2n).
__global__ __launch_bounds__(256) void step_kernel(int l) {
    __shared__ __align__(16) float As[2][16][SSTR];
    __shared__ __align__(16) float Bs[2][16][SSTR];
    int tid = threadIdx.x;
    int wid = tid >> 5, lane = tid & 31;
    int gid = lane >> 2, tig = lane & 3;
    int m0 = blockIdx.x * 128;
    int cb0 = blockIdx.y * 128;
    int wm = (wid & 3) * 32;
    int wn = (wid >> 2) * 64;

    float acc[2][8][4];
    #pragma unroll
    for (int mi = 0; mi < 2; mi++)
        #pragma unroll
        for (int ni = 0; ni < 8; ni++)
            #pragma unroll
            for (int r = 0; r < 4; r++) acc[mi][ni][r] = 0.0f;

    size_t xoff = (size_t)l * NN;
    int arow = tid >> 5;          // 0..7  (x/B row within half)
    int acol = (lane) * 4;        // 0..124
    int gm  = tid & 127;          // gh path: m within tile
    int gsel = tid >> 7;          // gh path: 0/1

    // LDG one chunk into registers. Half h (0/1) is x-path iff k_base<=128.
    auto ldg = [&](int ci, float4 v[4]) {
        int k0 = ci * 16;
        if (k0 <= 128)
            v[0] = *(const float4*)(g_x + (size_t)(k0 + arow) * LN + xoff + m0 + acol);
        else
            v[0] = *(const float4*)(g_gh + (size_t)(m0 + gm) * HP + (k0 - 136) + gsel * 4);
        if (k0 + 8 <= 128)
            v[1] = *(const float4*)(g_x + (size_t)(k0 + 8 + arow) * LN + xoff + m0 + acol);
        else
            v[1] = *(const float4*)(g_gh + (size_t)(m0 + gm) * HP + (k0 - 128) + gsel * 4);
        v[2] = *(const float4*)(g_W + (size_t)(k0 + arow) * GATES + cb0 + acol);
        v[3] = *(const float4*)(g_W + (size_t)(k0 + 8 + arow) * GATES + cb0 + acol);
    };
    auto sts = [&](int ci, int buf, float4 v[4]) {
        int k0 = ci * 16;
        if (k0 <= 128) {
            *(float4*)&As[buf][arow][acol] = v[0];
        } else {
            int r = gsel * 4;
            As[buf][r    ][gm] = v[0].x; As[buf][r + 1][gm] = v[0].y;
            As[buf][r + 2][gm] = v[0].z; As[buf][r + 3][gm] = v[0].w;
        }
        if (k0 + 8 <= 128) {
            *(float4*)&As[buf][8 + arow][acol] = v[1];
        } else {
            int r = 8 + gsel * 4;
            As[buf][r    ][gm] = v[1].x; As[buf][r + 1][gm] = v[1].y;
            As[buf][r + 2][gm] = v[1].z; As[buf][r + 3][gm] = v[1].w;
        }
        *(float4*)&Bs[buf][arow][acol]     = v[2];
        *(float4*)&Bs[buf][8 + arow][acol] = v[3];
    };

    float4 v[4];
    ldg(0, v);
    sts(0, 0, v);
    __syncthreads();

    #pragma unroll
    for (int ci = 0; ci < 17; ci++) {
        int buf = ci & 1;
        float4 nv[4];
        if (ci < 16) ldg(ci + 1, nv);

        unsigned a[2][4];
        #pragma unroll
        for (int mi = 0; mi < 2; mi++) {
            int mr = wm + mi * 16 + gid;
            a[mi][0] = pk(As[buf][2*tig    ][mr    ], As[buf][2*tig + 1][mr    ]);
            a[mi][1] = pk(As[buf][2*tig    ][mr + 8], As[buf][2*tig + 1][mr + 8]);
            a[mi][2] = pk(As[buf][2*tig + 8][mr    ], As[buf][2*tig + 9][mr    ]);
            a[mi][3] = pk(As[buf][2*tig + 8][mr + 8], As[buf][2*tig + 9][mr + 8]);
        }
        #pragma unroll
        for (int ni = 0; ni < 8; ni++) {
            int nc = wn + ni * 8 + gid;
            unsigned b0 = pk(Bs[buf][2*tig    ][nc], Bs[buf][2*tig + 1][nc]);
            unsigned b1 = pk(Bs[buf][2*tig + 8][nc], Bs[buf][2*tig + 9][nc]);
            #pragma unroll
            for (int mi = 0; mi < 2; mi++) {
                asm volatile(
                    "mma.sync.aligned.m16n8k16.row.col.f32.bf16.bf16.f32 "
                    "{%0,%1,%2,%3}, {%4,%5,%6,%7}, {%8,%9}, {%0,%1,%2,%3};"
                    : "+f"(acc[mi][ni][0]), "+f"(acc[mi][ni][1]),
                      "+f"(acc[mi][ni][2]), "+f"(acc[mi][ni][3])
                    : "r"(a[mi][0]), "r"(a[mi][1]), "r"(a[mi][2]), "r"(a[mi][3]),
                      "r"(b0), "r"(b1));
            }
        }
        if (ci < 16) {
            sts(ci + 1, buf ^ 1, nv);
            __syncthreads();
        }
    }

    // ---- fused cell epilogue (node-major h/c) ----
    #pragma unroll
    for (int mi = 0; mi < 2; mi++) {
        int r0 = m0 + wm + mi * 16 + gid;
        #pragma unroll
        for (int ni = 0; ni < 8; ni++) {
            int c = cb0 + wn + ni * 8 + 2 * tig;
            float cbv0 = __ldg(&g_cbias[c]);
            float cbv1 = __ldg(&g_cbias[c + 1]);
            float v0 = acc[mi][ni][0] + cbv0;
            float v1 = acc[mi][ni][1] + cbv1;
            float v2 = acc[mi][ni][2] + cbv0;
            float v3 = acc[mi][ni][3] + cbv1;
            float p0 = __shfl_xor_sync(0xffffffffu, v0, 1);
            float p1 = __shfl_xor_sync(0xffffffffu, v1, 1);
            float p2 = __shfl_xor_sync(0xffffffffu, v2, 1);
            float p3 = __shfl_xor_sync(0xffffffffu, v3, 1);
            int d = c >> 2;
            int row; float iv, fv, gv, ov;
            if ((tig & 1) == 0) { row = r0;     iv = v0; fv = v1; gv = p0; ov = p1; }
            else                { row = r0 + 8; iv = p2; fv = p3; gv = v2; ov = v3; }
            float gc = g_gc[(size_t)row * HD + d];
            float cn = sigf(fv) * gc + sigf(iv) * tanhf(gv);
            g_c[(size_t)row * HD + d] = cn;
            g_h[(size_t)row * HP + d] = sigf(ov) * tanhf(cn);
        }
    }
}

// ---------------- head MLP ----------------
__global__ void head_kernel(const float* __restrict__ W1, const float* __restrict__ b1,
                            const float* __restrict__ W2, const float* __restrict__ b2,
                            float* __restrict__ out, int rows)
{
    __shared__ float sW1[20 * 128];
    __shared__ float sb1[20], sW2[20];
    __shared__ float sb2;
    int tid = threadIdx.x;
    for (int i = tid; i < 20 * 128; i += 256) sW1[i] = W1[i];
    if (tid < 20) { sb1[tid] = b1[tid]; sW2[tid] = W2[tid]; }
    if (tid == 0) sb2 = b2[0];
    __syncthreads();
    int b = blockIdx.x * 256 + tid;
    if (b >= rows) return;
    float z1[20];
    #pragma unroll
    for (int j = 0; j < 20; j++) z1[j] = sb1[j];
    const float* hrow = g_h + (size_t)b * HP;
    for (int k = 0; k < 128; k++) {
        float hv = hrow[k];
        #pragma unroll
        for (int j = 0; j < 20; j++) z1[j] += hv * sW1[j * 128 + k];
    }
    float z = sb2;
    #pragma unroll
    for (int j = 0; j < 20; j++) z += z1[j] * sW2[j];
    out[b] = 1.0f / (1.0f + expf(-z));
}

// ---------------- launch ----------------
extern "C" void kernel_launch(void* const* d_in, const int* in_sizes, int n_in,
                              void* d_out, int out_size)
{
    const float* op    = (const float*)d_in[0];
    const float* attr  = (const float*)d_in[1];
    const float* filt  = (const float*)d_in[2];
    const float* outp  = (const float*)d_in[3];
    const int*   mapping = (const int*)d_in[4];
    int wb = (in_sizes[5] == 1) ? 6 : 5;
    const float* Wf    = (const float*)d_in[wb + 0];
    const float* bf    = (const float*)d_in[wb + 1];
    const float* Wo    = (const float*)d_in[wb + 2];
    const float* bo    = (const float*)d_in[wb + 3];
    const float* g1    = (const float*)d_in[wb + 4];
    const float* beta1 = (const float*)d_in[wb + 5];
    const float* g2    = (const float*)d_in[wb + 6];
    const float* beta2 = (const float*)d_in[wb + 7];
    const float* Wih   = (const float*)d_in[wb + 8];
    const float* Whh   = (const float*)d_in[wb + 9];
    const float* bih   = (const float*)d_in[wb + 10];
    const float* bhh   = (const float*)d_in[wb + 11];
    const float* W1    = (const float*)d_in[wb + 12];
    const float* b1    = (const float*)d_in[wb + 13];
    const float* W2    = (const float*)d_in[wb + 14];
    const float* b2    = (const float*)d_in[wb + 15];
    float* outptr = (float*)d_out;

    size_t ztotal = (size_t)NN * (HP + HD + HP);
    zero_kernel<<<(int)((ztotal + 255) / 256), 256>>>();
    build_x_kernel<<<LN / 256, 256>>>(op, attr, filt, outp, Wf, bf, Wo, bo);
    stats_kernel<<<dim3(64, 12), 256>>>();
    fold_kernel<<<1, 64>>>(g1, beta1, g2, beta2);
    cbias_kernel<<<1, 512>>>(Wih, bih, bhh);
    weight_kernel<<<KPAD, 512>>>(Wih, Whh);

    for (int t = 0; t < L_STEPS; t++) {
        int l = L_STEPS - 1 - t;
        gather_kernel<<<NN / 8, 256>>>(mapping, l);
        step_kernel<<<dim3(NN / 128, GATES / 128), 256>>>(l);
    }

    head_kernel<<<(out_size + 255) / 256, 256>>>(W1, b1, W2, b2, outptr, out_size);
}